// round 17
// baseline (speedup 1.0000x reference)
#include <cuda_runtime.h>
#include <cuda_bf16.h>
#include <cstdint>

// NCCLayer argmax: single fused kernel. 2-way bf16 split HMMA + mantissa-
// embedded-index argmax + in-CTA exact rescue. R16 lesson: alu pipe is at its
// ~31us floor; the other ~42us was wave-quantization tail (1024 CTAs @ 1.4+
// waves) + prep launch + DRAM round-trips. R17: 512 CTAs (one wave) x 256
// rows (B staging amortized 2x), prep fused in-kernel, zero scratch tensors.

#define KK    16
#define DD    1024
#define NTOT  131072
#define TPB   256
#define RPC   256                  // rows per CTA
#define NBLK  (NTOT / RPC)         // 512 CTAs = one wave
#define MARGINQ 3e-4f              // >= 2*delta_mma (~3.3e-5) + 2*quant (1.22e-4)

__device__ __forceinline__ void split2(float v, __nv_bfloat16& h1, __nv_bfloat16& h2) {
    h1 = __float2bfloat16(v);
    h2 = __float2bfloat16(v - __bfloat162float(h1));
}
__device__ __forceinline__ uint32_t pkbf(__nv_bfloat16 lo, __nv_bfloat16 hi) {
    return (uint32_t)__bfloat16_as_ushort(lo) | ((uint32_t)__bfloat16_as_ushort(hi) << 16);
}
__device__ __forceinline__ void mma16816(float& d0, float& d1, float& d2, float& d3,
                                         uint32_t a0, uint32_t a1, uint32_t a2,
                                         uint32_t a3, uint32_t b0, uint32_t b1) {
    asm volatile(
        "mma.sync.aligned.m16n8k16.row.col.f32.bf16.bf16.f32 "
        "{%0,%1,%2,%3}, {%4,%5,%6,%7}, {%8,%9}, {%0,%1,%2,%3};"
        : "+f"(d0), "+f"(d1), "+f"(d2), "+f"(d3)
        : "r"(a0), "r"(a1), "r"(a2), "r"(a3), "r"(b0), "r"(b1));
}
// value already biased positive (+4 via accumulator init): pure bit-splice
__device__ __forceinline__ float embed(float v, uint32_t code) {
    return __uint_as_float((__float_as_uint(v) & 0xFFFFFF00u) | code);
}

__global__ __launch_bounds__(TPB) void ncc_fused_kernel(
    const float* __restrict__ x,
    const float* __restrict__ cmat,
    float* __restrict__ out)
{
    // 32KB: A-frag staging (16KB, transient) then per-phase B frag-pack (32KB).
    __shared__ char smem[512 * 64];
    __shared__ int scount;
    __shared__ int sflag[256];

    const int tid = threadIdx.x;
    const int wid = tid >> 5;
    const int lid = tid & 31;
    const int t   = lid & 3;     // quad pos
    const int r   = lid >> 2;    // group row / B col

    if (tid == 0) scount = 0;

    // ======== A prep: thread tid normalizes row (blk*256 + tid) ========
    {
        const int n = blockIdx.x * RPC + tid;
        float a[KK];
        float s = 0.f;
        #pragma unroll
        for (int k = 0; k < KK; ++k) { a[k] = x[k * NTOT + n]; s += a[k]; }
        const float mu = s * (1.0f / KK);
        float ss = 0.f;
        #pragma unroll
        for (int k = 0; k < KK; ++k) { a[k] -= mu; ss += a[k] * a[k]; }
        const float inv = 1.0f / (sqrtf(ss) + 1e-10f);
        __nv_bfloat16 h1[KK], h2[KK];
        #pragma unroll
        for (int k = 0; k < KK; ++k) split2(a[k] * inv, h1[k], h2[k]);
        // layout: row*64 + split*32 + k*2
        uint4* dst = (uint4*)(smem + tid * 64);
        dst[0] = make_uint4(pkbf(h1[0],h1[1]), pkbf(h1[2],h1[3]), pkbf(h1[4],h1[5]), pkbf(h1[6],h1[7]));
        dst[1] = make_uint4(pkbf(h1[8],h1[9]), pkbf(h1[10],h1[11]), pkbf(h1[12],h1[13]), pkbf(h1[14],h1[15]));
        dst[2] = make_uint4(pkbf(h2[0],h2[1]), pkbf(h2[2],h2[3]), pkbf(h2[4],h2[5]), pkbf(h2[6],h2[7]));
        dst[3] = make_uint4(pkbf(h2[8],h2[9]), pkbf(h2[10],h2[11]), pkbf(h2[12],h2[13]), pkbf(h2[14],h2[15]));
    }
    __syncthreads();

    // ---- A fragments for 2 row-batches (b*128 + wid*16 + r, +8), 2 splits ----
    uint32_t af[2][2][4];   // [batch][split][frag]
    #pragma unroll
    for (int b = 0; b < 2; ++b) {
        const char* baseA = smem + (b * 128 + wid * 16 + r) * 64;
        const char* baseB = baseA + 8 * 64;
        #pragma unroll
        for (int s = 0; s < 2; ++s) {
            af[b][s][0] = *(const uint32_t*)(baseA + s * 32 + 4 * t);
            af[b][s][1] = *(const uint32_t*)(baseB + s * 32 + 4 * t);
            af[b][s][2] = *(const uint32_t*)(baseA + s * 32 + 4 * t + 16);
            af[b][s][3] = *(const uint32_t*)(baseB + s * 32 + 4 * t + 16);
        }
    }

    // running embedded top-2: [batch][rowhalf]
    float best[2][2] = {{0.f, 0.f}, {0.f, 0.f}};
    float sec [2][2] = {{0.f, 0.f}, {0.f, 0.f}};

    #pragma unroll
    for (int ph = 0; ph < 2; ++ph) {
        __syncthreads();   // A frags consumed / previous phase sweep done

        // ======== B prep: 2 cols/thread, exact chain + frag-pack ========
        #pragma unroll
        for (int c = 0; c < 2; ++c) {
            const int dl = c * 256 + tid;
            const int d  = ph * 512 + dl;
            float b[KK];
            float s = 0.f;
            #pragma unroll
            for (int k = 0; k < KK; ++k) { b[k] = cmat[k * DD + d]; s += b[k]; }
            const float mu = s * (1.0f / KK);
            float ss = 0.f;
            #pragma unroll
            for (int k = 0; k < KK; ++k) { b[k] -= mu; ss += b[k] * b[k]; }
            const float inv = 1.0f / (sqrtf(ss) + 1e-10f);
            __nv_bfloat16 lb[32];
            #pragma unroll
            for (int k = 0; k < KK; ++k) {
                __nv_bfloat16 h1, h2;
                split2(b[k] * inv, h1, h2);
                // interleaved frag-pack: quad p=(k&7)>>1; 16B = [s0 x4 | s1 x4]
                const int p    = (k & 7) >> 1;
                const int slot = ((k >> 3) << 1) | (k & 1);
                lb[p * 8 + 0 + slot] = h1;
                lb[p * 8 + 4 + slot] = h2;
            }
            uint4* ob = (uint4*)(smem + dl * 64);
            #pragma unroll
            for (int q = 0; q < 4; ++q)
                ob[q] = make_uint4(pkbf(lb[q*8+0],lb[q*8+1]), pkbf(lb[q*8+2],lb[q*8+3]),
                                   pkbf(lb[q*8+4],lb[q*8+5]), pkbf(lb[q*8+6],lb[q*8+7]));
        }
        __syncthreads();

        // ======== sweep: 32 x (2 tiles x 2 row-batches) ========
        #pragma unroll 2
        for (int dt2 = 0; dt2 < 32; ++dt2) {
            const int dgl = dt2 * 16;
            const uint32_t cb = 255u - 4u * (uint32_t)(ph * 32 + dt2);

            const uint4 qa = *(const uint4*)(smem + (dgl + r) * 64 + t * 16);
            const uint4 qb = *(const uint4*)(smem + (dgl + 8 + r) * 64 + t * 16);

            #pragma unroll
            for (int b = 0; b < 2; ++b) {
                float pa0=4.f,pa1=4.f,pa2=4.f,pa3=4.f, sa0=0.f,sa1=0.f,sa2=0.f,sa3=0.f;
                float pb0=4.f,pb1=4.f,pb2=4.f,pb3=4.f, sb0=0.f,sb1=0.f,sb2=0.f,sb3=0.f;
                mma16816(pa0,pa1,pa2,pa3, af[b][0][0],af[b][0][1],af[b][0][2],af[b][0][3], qa.x, qa.y);
                mma16816(sa0,sa1,sa2,sa3, af[b][0][0],af[b][0][1],af[b][0][2],af[b][0][3], qa.z, qa.w);
                mma16816(sa0,sa1,sa2,sa3, af[b][1][0],af[b][1][1],af[b][1][2],af[b][1][3], qa.x, qa.y);
                mma16816(pb0,pb1,pb2,pb3, af[b][0][0],af[b][0][1],af[b][0][2],af[b][0][3], qb.x, qb.y);
                mma16816(sb0,sb1,sb2,sb3, af[b][0][0],af[b][0][1],af[b][0][2],af[b][0][3], qb.z, qb.w);
                mma16816(sb0,sb1,sb2,sb3, af[b][1][0],af[b][1][1],af[b][1][2],af[b][1][3], qb.x, qb.y);

                // rowhalf 0
                {
                    const float f0 = embed(pa0 + sa0, cb);
                    const float f1 = embed(pa1 + sa1, cb - 1u);
                    const float f2 = embed(pb0 + sb0, cb - 2u);
                    const float f3 = embed(pb1 + sb1, cb - 3u);
                    const float m01 = fmaxf(f0, f1), n01 = fminf(f0, f1);
                    const float m23 = fmaxf(f2, f3), n23 = fminf(f2, f3);
                    const float gm = fmaxf(m01, m23);
                    const float gs = fmaxf(fminf(m01, m23), fmaxf(n01, n23));
                    sec[b][0]  = fmaxf(sec[b][0], fmaxf(fminf(best[b][0], gm), gs));
                    best[b][0] = fmaxf(best[b][0], gm);
                }
                // rowhalf 1
                {
                    const float f0 = embed(pa2 + sa2, cb);
                    const float f1 = embed(pa3 + sa3, cb - 1u);
                    const float f2 = embed(pb2 + sb2, cb - 2u);
                    const float f3 = embed(pb3 + sb3, cb - 3u);
                    const float m01 = fmaxf(f0, f1), n01 = fminf(f0, f1);
                    const float m23 = fmaxf(f2, f3), n23 = fminf(f2, f3);
                    const float gm = fmaxf(m01, m23);
                    const float gs = fmaxf(fminf(m01, m23), fmaxf(n01, n23));
                    sec[b][1]  = fmaxf(sec[b][1], fmaxf(fminf(best[b][1], gm), gs));
                    best[b][1] = fmaxf(best[b][1], gm);
                }
            }
        }
    }

    // ======== per-combo: recover col, butterfly, emit, flag ========
    #pragma unroll
    for (int b = 0; b < 2; ++b) {
        #pragma unroll
        for (int h = 0; h < 2; ++h) {
            float bb = best[b][h], ssv = sec[b][h];
            const float myb = bb;
            const uint32_t pos = 255u - (__float_as_uint(bb) & 255u);
            const int col = (int)((pos >> 1) * 8 + (pos & 1)) + 2 * t;

            #pragma unroll
            for (int m = 1; m <= 2; m <<= 1) {
                const float ob = __shfl_xor_sync(0xffffffffu, bb,  m);
                const float os = __shfl_xor_sync(0xffffffffu, ssv, m);
                ssv = fmaxf(fminf(bb, ob), fmaxf(ssv, os));
                bb  = fmaxf(bb, ob);
            }
            int cand = (myb == bb) ? col : 0x7fffffff;
            #pragma unroll
            for (int m = 1; m <= 2; m <<= 1)
                cand = min(cand, __shfl_xor_sync(0xffffffffu, cand, m));

            if (t == 0) {
                const int n = blockIdx.x * RPC + b * 128 + wid * 16 + r + h * 8;
                out[n] = (float)cand;
                const float bq = __uint_as_float(__float_as_uint(bb)  & 0xFFFFFF00u);
                const float sq = __uint_as_float(__float_as_uint(ssv) & 0xFFFFFF00u);
                if (bq - sq < MARGINQ) sflag[atomicAdd(&scount, 1)] = n;
            }
        }
    }
    __syncthreads();

    // ======== in-CTA exact rescue (verbatim R5 fp32 chains) ========
    const int cnt = scount;
    if (cnt == 0) return;

    float* rval = (float*)smem;
    int*   ridx = (int*)(smem + TPB * 4);

    for (int f = 0; f < cnt; ++f) {
        const int n = sflag[f];

        float a[KK];
        float s = 0.f;
        #pragma unroll
        for (int k = 0; k < KK; ++k) { a[k] = x[k * NTOT + n]; s += a[k]; }
        const float mu = s * (1.0f / KK);
        float ss = 0.f;
        #pragma unroll
        for (int k = 0; k < KK; ++k) { a[k] -= mu; ss += a[k] * a[k]; }
        const float inv = 1.0f / (sqrtf(ss) + 1e-10f);
        #pragma unroll
        for (int k = 0; k < KK; ++k) a[k] *= inv;

        float bestv = -3.0e38f;
        int   bi    = 0;
        #pragma unroll
        for (int j = 0; j < 4; ++j) {
            const int d = tid * 4 + j;          // ascending within thread
            // exact b-normalization (identical op chain to R5; cmat L2-hot)
            float b[KK];
            float s2 = 0.f;
            #pragma unroll
            for (int k = 0; k < KK; ++k) { b[k] = cmat[k * DD + d]; s2 += b[k]; }
            const float mu2 = s2 * (1.0f / KK);
            float ss2 = 0.f;
            #pragma unroll
            for (int k = 0; k < KK; ++k) { b[k] -= mu2; ss2 += b[k] * b[k]; }
            const float inv2 = 1.0f / (sqrtf(ss2) + 1e-10f);
            float acc = 0.f;
            #pragma unroll
            for (int k = 0; k < KK; ++k) acc = fmaf(a[k], b[k] * inv2, acc);
            if (acc > bestv) { bestv = acc; bi = d; }   // strict > = first occ.
        }
        rval[tid] = bestv;
        ridx[tid] = bi;
        __syncthreads();
        #pragma unroll
        for (int sdt = TPB / 2; sdt >= 1; sdt >>= 1) {
            if (tid < sdt) {
                const float ov = rval[tid + sdt];
                const int   oi = ridx[tid + sdt];
                if (ov > rval[tid] || (ov == rval[tid] && oi < ridx[tid])) {
                    rval[tid] = ov;
                    ridx[tid] = oi;
                }
            }
            __syncthreads();
        }
        if (tid == 0) out[n] = (float)ridx[0];
        __syncthreads();
    }
}

extern "C" void kernel_launch(void* const* d_in, const int* in_sizes, int n_in,
                              void* d_out, int out_size)
{
    // Select inputs by element count — immune to metadata ordering.
    const float* x;
    const float* cmat;
    if (in_sizes[0] >= in_sizes[1]) {
        x    = (const float*)d_in[0];
        cmat = (const float*)d_in[1];
    } else {
        x    = (const float*)d_in[1];
        cmat = (const float*)d_in[0];
    }
    float* out = (float*)d_out;

    ncc_fused_kernel<<<NBLK, TPB>>>(x, cmat, out);
}